// round 16
// baseline (speedup 1.0000x reference)
#include <cuda_runtime.h>
#include <cuda_bf16.h>

// B=4, H=16, L=8192, D=64
#define BH_    64
#define H_     16
#define L_     8192
#define D_     64
#define TILE_  256                 // positions per tile (block)
#define NT_    32                  // tiles per (b,h) chain
#define NBLK_  (BH_ * NT_)         // 2048
#define EPS_   1e-6f

// Decoupled-lookback state with EPOCH-ENCODED flags (never reset):
// after launch n, every flag holds 2n. During launch n: agg = 2n-1, incl = 2n.
// A block derives n from its own flag at entry (only the owner writes it).
__device__ int   g_ticket;                       // monotonic across launches
__device__ int   g_flag[NBLK_];                  // zero-init => launch 1 => n=1
__device__ float g_aggr[(size_t)NBLK_ * 256];    // [128 k-sum | 128 kv-sum]
__device__ float g_incl[(size_t)NBLK_ * 256];

__device__ __forceinline__ float phi(float x) {
    return x > 0.0f ? x + 1.0f : __expf(x);
}

// Partial evict_last policy: at 8 blocks/SM full pinning would mark ~151MB
// (> L2); 0.5 keeps the protected set ~76MB so it actually survives.
__device__ __forceinline__ unsigned long long mk_evict_last_policy() {
    unsigned long long pol;
    asm("createpolicy.fractional.L2::evict_last.b64 %0, 0.5;" : "=l"(pol));
    return pol;
}
__device__ __forceinline__ float4 ld_keep4(const float* p, unsigned long long pol) {
    float4 r;
    asm("ld.global.nc.L2::cache_hint.v4.f32 {%0,%1,%2,%3}, [%4], %5;"
        : "=f"(r.x), "=f"(r.y), "=f"(r.z), "=f"(r.w) : "l"(p), "l"(pol));
    return r;
}
__device__ __forceinline__ float4 ld_stream4(const float* p) {
    float4 r;
    asm("ld.global.cs.nc.v4.f32 {%0,%1,%2,%3}, [%4];"
        : "=f"(r.x), "=f"(r.y), "=f"(r.z), "=f"(r.w) : "l"(p));
    return r;
}
__device__ __forceinline__ void st_stream4(float* p, float4 v) {
    asm volatile("st.global.cs.v4.f32 [%0], {%1,%2,%3,%4};"
                 :: "l"(p), "f"(v.x), "f"(v.y), "f"(v.z), "f"(v.w) : "memory");
}

// ---------------------------------------------------------------------------
// Fused single-pass scan (epoch flags, single kernel/launch). 8 blocks/SM
// (64 warps = HW max) to hide phase-A DRAM latency and lookback bubbles.
// Thread map: g = t>>4 owns positions [g*16, g*16+16); d4 = t&15 owns channel
// quad d4*4..d4*4+3.
// ---------------------------------------------------------------------------
__global__ void __launch_bounds__(256, 8) la_fused(
    const float* __restrict__ qp, const float* __restrict__ kp,
    const float* __restrict__ vp, const float* __restrict__ mp,
    float* __restrict__ op)
{
    __shared__ float s_k [16][128];   // group sums -> exclusive group prefixes
    __shared__ float s_kv[16][128];
    __shared__ float s_tot[256];      // tile totals   [k | kv]
    __shared__ float s_chain[256];    // chain prefix  [k | kv]
    __shared__ int   s_tile, s_n, s_msg;

    const int t = threadIdx.x;
    if (t == 0) {
        int ticket = atomicAdd(&g_ticket, 1);
        int tl = ticket & (NBLK_ - 1);          // chain-interleaved mapping
        s_tile = tl;
        s_n    = g_flag[tl] / 2 + 1;            // epoch n (owner-only read)
    }
    __syncthreads();
    const int tile = s_tile;
    const int n    = s_n;
    const int fAGG = 2 * n - 1, fINC = 2 * n;
    const int bh   = tile & (BH_ - 1);
    const int ti   = tile >> 6;
    const int b    = bh >> 4;
    const int g    = t >> 4;
    const int d4   = t & 15;
    const int l0   = ti * TILE_ + g * 16;
    const size_t base = ((size_t)bh * L_ + l0) * D_ + d4 * 4;
    const float* mrow = mp + b * L_ + l0;
    const unsigned long long pol = mk_evict_last_policy();

    // ---- Phase A: group sums of masked phi(k), phi(k)*v (partly pinned) ----
    float4 sk  = make_float4(0.f, 0.f, 0.f, 0.f);
    float4 skv = make_float4(0.f, 0.f, 0.f, 0.f);
    #pragma unroll 4
    for (int i = 0; i < 16; ++i) {
        float4 kk = ld_keep4(kp + base + (size_t)i * D_, pol);
        float4 vv = ld_keep4(vp + base + (size_t)i * D_, pol);
        float  m  = mrow[i];
        float a0 = phi(kk.x) * m, a1 = phi(kk.y) * m,
              a2 = phi(kk.z) * m, a3 = phi(kk.w) * m;
        sk.x += a0; sk.y += a1; sk.z += a2; sk.w += a3;
        skv.x += a0 * (vv.x * m); skv.y += a1 * (vv.y * m);
        skv.z += a2 * (vv.z * m); skv.w += a3 * (vv.w * m);
    }
    *(float4*)&s_k [g][d4 * 4] = sk;
    *(float4*)&s_kv[g][d4 * 4] = skv;
    __syncthreads();

    // ---- Intra-tile scan over the 16 groups (t<128: k, t>=128: kv) ----
    {
        float run = 0.f;
        if (t < 128) {
            const int c = t;
            #pragma unroll
            for (int g2 = 0; g2 < 16; ++g2) {
                float x = s_k[g2][c]; s_k[g2][c] = run; run += x;
            }
        } else {
            const int c = t - 128;
            #pragma unroll
            for (int g2 = 0; g2 < 16; ++g2) {
                float x = s_kv[g2][c]; s_kv[g2][c] = run; run += x;
            }
        }
        s_tot[t] = run;
        if (ti > 0) g_aggr[(size_t)tile * 256 + t] = run;
        s_chain[t] = 0.f;
    }
    __syncthreads();
    if (ti > 0) {
        __threadfence();
        if (t == 0) atomicExch(&g_flag[tile], fAGG);
    }

    // ---- Decoupled lookback (single flag per tile; thread 0 polls) ----
    if (ti > 0) {
        volatile int* vf = (volatile int*)g_flag;
        int p = tile - BH_;
        for (;;) {
            if (t == 0) {
                int f;
                while ((f = vf[p]) < fAGG) __nanosleep(64);
                s_msg = f;
            }
            __syncthreads();
            const int f = s_msg;
            __threadfence();   // acquire: order payload reads after flag read
            if (f == fINC) {
                s_chain[t] += g_incl[(size_t)p * 256 + t];
                break;
            }
            s_chain[t] += g_aggr[(size_t)p * 256 + t];
            p -= BH_;
            __syncthreads();
        }
    }
    __syncthreads();

    // ---- Publish inclusive prefix for successors ----
    g_incl[(size_t)tile * 256 + t] = s_chain[t] + s_tot[t];
    __syncthreads();
    __threadfence();
    if (t == 0) atomicExch(&g_flag[tile], fINC);

    // ---- Phase C: re-read own k,v from L2 (streaming), stream q, output ----
    float4 pk, pkv;
    {
        float4 ck  = *(const float4*)&s_chain[d4 * 4];
        float4 ckv = *(const float4*)&s_chain[128 + d4 * 4];
        float4 ek  = *(const float4*)&s_k [g][d4 * 4];
        float4 ekv = *(const float4*)&s_kv[g][d4 * 4];
        pk  = make_float4(ck.x + ek.x,  ck.y + ek.y,  ck.z + ek.z,  ck.w + ek.w);
        pkv = make_float4(ckv.x + ekv.x, ckv.y + ekv.y,
                          ckv.z + ekv.z, ckv.w + ekv.w);
    }

    #pragma unroll 4
    for (int i = 0; i < 16; ++i) {
        const size_t off = base + (size_t)i * D_;
        float4 kk = ld_stream4(kp + off);
        float4 vv = ld_stream4(vp + off);
        float4 qq = ld_stream4(qp + off);
        float  m  = mrow[i];

        float a0 = phi(kk.x) * m, a1 = phi(kk.y) * m,
              a2 = phi(kk.z) * m, a3 = phi(kk.w) * m;
        pk.x += a0; pk.y += a1; pk.z += a2; pk.w += a3;
        pkv.x += a0 * (vv.x * m); pkv.y += a1 * (vv.y * m);
        pkv.z += a2 * (vv.z * m); pkv.w += a3 * (vv.w * m);

        float q0 = phi(qq.x), q1 = phi(qq.y),
              q2 = phi(qq.z), q3 = phi(qq.w);

        float z = q0 * pk.x + q1 * pk.y + q2 * pk.z + q3 * pk.w;
        z += __shfl_xor_sync(0xffffffffu, z, 8);
        z += __shfl_xor_sync(0xffffffffu, z, 4);
        z += __shfl_xor_sync(0xffffffffu, z, 2);
        z += __shfl_xor_sync(0xffffffffu, z, 1);
        z = (z + EPS_) * m;
        float rz = 1.0f / z;

        float4 o;
        o.x = q0 * pkv.x * rz; o.y = q1 * pkv.y * rz;
        o.z = q2 * pkv.z * rz; o.w = q3 * pkv.w * rz;
        st_stream4(op + off, o);
    }
}

// ---------------------------------------------------------------------------
extern "C" void kernel_launch(void* const* d_in, const int* in_sizes, int n_in,
                              void* d_out, int out_size)
{
    const float* q = (const float*)d_in[0];
    const float* k = (const float*)d_in[1];
    const float* v = (const float*)d_in[2];
    const float* m = (const float*)d_in[3];
    float* out = (float*)d_out;

    la_fused<<<NBLK_, 256>>>(q, k, v, m, out);
}

// round 17
// speedup vs baseline: 1.1412x; 1.1412x over previous
#include <cuda_runtime.h>
#include <cuda_bf16.h>

// B=4, H=16, L=8192, D=64
#define BH_    64
#define H_     16
#define L_     8192
#define D_     64
#define TILE_  256                 // positions per tile (block)
#define NT_    32                  // tiles per (b,h) chain
#define NBLK_  (BH_ * NT_)         // 2048
#define EPS_   1e-6f

// Decoupled-lookback state with EPOCH-ENCODED flags (never reset):
// after launch n, every flag holds 2n. During launch n: agg = 2n-1, incl = 2n.
__device__ int   g_ticket;                       // monotonic across launches
__device__ int   g_flag[NBLK_];                  // zero-init => launch 1 => n=1
__device__ float g_aggr[(size_t)NBLK_ * 256];    // [128 k-sum | 128 kv-sum]
__device__ float g_incl[(size_t)NBLK_ * 256];

__device__ __forceinline__ float phi(float x) {
    return x > 0.0f ? x + 1.0f : __expf(x);
}

__device__ __forceinline__ unsigned long long mk_evict_last_policy() {
    unsigned long long pol;
    asm("createpolicy.fractional.L2::evict_last.b64 %0, 0.75;" : "=l"(pol));
    return pol;
}
__device__ __forceinline__ float4 ld_keep4(const float* p, unsigned long long pol) {
    float4 r;
    asm("ld.global.nc.L2::cache_hint.v4.f32 {%0,%1,%2,%3}, [%4], %5;"
        : "=f"(r.x), "=f"(r.y), "=f"(r.z), "=f"(r.w) : "l"(p), "l"(pol));
    return r;
}
__device__ __forceinline__ float4 ld_stream4(const float* p) {
    float4 r;
    asm("ld.global.cs.nc.v4.f32 {%0,%1,%2,%3}, [%4];"
        : "=f"(r.x), "=f"(r.y), "=f"(r.z), "=f"(r.w) : "l"(p));
    return r;
}
__device__ __forceinline__ void st_stream4(float* p, float4 v) {
    asm volatile("st.global.cs.v4.f32 [%0], {%1,%2,%3,%4};"
                 :: "l"(p), "f"(v.x), "f"(v.y), "f"(v.z), "f"(v.w) : "memory");
}
// Scoped-atomic message passing (replaces full __threadfence per round):
// publisher: payload stores -> __syncthreads -> release-exch by thread 0.
// consumer:  acquire-load by thread 0 -> __syncthreads -> payload loads.
__device__ __forceinline__ int ld_acquire_gpu(const int* p) {
    int v;
    asm volatile("ld.global.acquire.gpu.b32 %0, [%1];" : "=r"(v) : "l"(p) : "memory");
    return v;
}
__device__ __forceinline__ void st_release_gpu(int* p, int v) {
    int old;
    asm volatile("atom.global.release.gpu.exch.b32 %0, [%1], %2;"
                 : "=r"(old) : "l"(p), "r"(v) : "memory");
}

// ---------------------------------------------------------------------------
// Fused single-pass scan (R15 base). Changes: (1) acquire/release scoped
// atomics replace full __threadfence in the lookback hot path; (2) mask
// staged once through smem instead of 32 scalar LDGs per thread.
// Thread map: g = t>>4 owns positions [g*16, g*16+16); d4 = t&15 owns channel
// quad d4*4..d4*4+3.
// ---------------------------------------------------------------------------
__global__ void __launch_bounds__(256, 6) la_fused(
    const float* __restrict__ qp, const float* __restrict__ kp,
    const float* __restrict__ vp, const float* __restrict__ mp,
    float* __restrict__ op)
{
    __shared__ float s_k [16][128];   // group sums -> exclusive group prefixes
    __shared__ float s_kv[16][128];
    __shared__ float s_tot[256];      // tile totals   [k | kv]
    __shared__ float s_chain[256];    // chain prefix  [k | kv]
    __shared__ float s_m[256];        // tile mask
    __shared__ int   s_tile, s_n, s_msg;

    const int t = threadIdx.x;
    if (t == 0) {
        int ticket = atomicAdd(&g_ticket, 1);
        int tl = ticket & (NBLK_ - 1);          // chain-interleaved mapping
        s_tile = tl;
        s_n    = g_flag[tl] / 2 + 1;            // epoch n (owner-only read)
    }
    __syncthreads();
    const int tile = s_tile;
    const int n    = s_n;
    const int fAGG = 2 * n - 1, fINC = 2 * n;
    const int bh   = tile & (BH_ - 1);
    const int ti   = tile >> 6;
    const int b    = bh >> 4;
    const int g    = t >> 4;
    const int d4   = t & 15;
    const int l0   = ti * TILE_ + g * 16;
    const size_t base = ((size_t)bh * L_ + l0) * D_ + d4 * 4;
    const unsigned long long pol = mk_evict_last_policy();

    // Stage the tile's mask once (coalesced; replaces per-thread scalar LDGs)
    s_m[t] = mp[b * L_ + ti * TILE_ + t];
    __syncthreads();
    const float* mrow = &s_m[g * 16];

    // ---- Phase A: group sums of masked phi(k), phi(k)*v (mostly pinned) ----
    float4 sk  = make_float4(0.f, 0.f, 0.f, 0.f);
    float4 skv = make_float4(0.f, 0.f, 0.f, 0.f);
    #pragma unroll 4
    for (int i = 0; i < 16; ++i) {
        float4 kk = ld_keep4(kp + base + (size_t)i * D_, pol);
        float4 vv = ld_keep4(vp + base + (size_t)i * D_, pol);
        float  m  = mrow[i];
        float a0 = phi(kk.x) * m, a1 = phi(kk.y) * m,
              a2 = phi(kk.z) * m, a3 = phi(kk.w) * m;
        sk.x += a0; sk.y += a1; sk.z += a2; sk.w += a3;
        skv.x += a0 * (vv.x * m); skv.y += a1 * (vv.y * m);
        skv.z += a2 * (vv.z * m); skv.w += a3 * (vv.w * m);
    }
    *(float4*)&s_k [g][d4 * 4] = sk;
    *(float4*)&s_kv[g][d4 * 4] = skv;
    __syncthreads();

    // ---- Intra-tile scan over the 16 groups (t<128: k, t>=128: kv) ----
    {
        float run = 0.f;
        if (t < 128) {
            const int c = t;
            #pragma unroll
            for (int g2 = 0; g2 < 16; ++g2) {
                float x = s_k[g2][c]; s_k[g2][c] = run; run += x;
            }
        } else {
            const int c = t - 128;
            #pragma unroll
            for (int g2 = 0; g2 < 16; ++g2) {
                float x = s_kv[g2][c]; s_kv[g2][c] = run; run += x;
            }
        }
        s_tot[t] = run;
        if (ti > 0) g_aggr[(size_t)tile * 256 + t] = run;
        s_chain[t] = 0.f;
    }
    __syncthreads();                     // aggregate stores complete
    if (ti > 0 && t == 0) st_release_gpu(&g_flag[tile], fAGG);

    // ---- Decoupled lookback (acquire poll by thread 0) ----
    if (ti > 0) {
        int p = tile - BH_;
        for (;;) {
            if (t == 0) {
                int f;
                while ((f = ld_acquire_gpu(&g_flag[p])) < fAGG) __nanosleep(64);
                s_msg = f;
            }
            __syncthreads();             // bridges t0's acquire to all threads
            const int f = s_msg;
            if (f == fINC) {
                s_chain[t] += g_incl[(size_t)p * 256 + t];
                break;
            }
            s_chain[t] += g_aggr[(size_t)p * 256 + t];
            p -= BH_;
            __syncthreads();
        }
    }
    __syncthreads();

    // ---- Publish inclusive prefix for successors ----
    g_incl[(size_t)tile * 256 + t] = s_chain[t] + s_tot[t];
    __syncthreads();                     // inclusive stores complete
    if (t == 0) st_release_gpu(&g_flag[tile], fINC);

    // ---- Phase C: re-read own k,v from L2 (streaming), stream q, output ----
    float4 pk, pkv;
    {
        float4 ck  = *(const float4*)&s_chain[d4 * 4];
        float4 ckv = *(const float4*)&s_chain[128 + d4 * 4];
        float4 ek  = *(const float4*)&s_k [g][d4 * 4];
        float4 ekv = *(const float4*)&s_kv[g][d4 * 4];
        pk  = make_float4(ck.x + ek.x,  ck.y + ek.y,  ck.z + ek.z,  ck.w + ek.w);
        pkv = make_float4(ckv.x + ekv.x, ckv.y + ekv.y,
                          ckv.z + ekv.z, ckv.w + ekv.w);
    }

    #pragma unroll 4
    for (int i = 0; i < 16; ++i) {
        const size_t off = base + (size_t)i * D_;
        float4 kk = ld_stream4(kp + off);
        float4 vv = ld_stream4(vp + off);
        float4 qq = ld_stream4(qp + off);
        float  m  = mrow[i];

        float a0 = phi(kk.x) * m, a1 = phi(kk.y) * m,
              a2 = phi(kk.z) * m, a3 = phi(kk.w) * m;
        pk.x += a0; pk.y += a1; pk.z += a2; pk.w += a3;
        pkv.x += a0 * (vv.x * m); pkv.y += a1 * (vv.y * m);
        pkv.z += a2 * (vv.z * m); pkv.w += a3 * (vv.w * m);

        float q0 = phi(qq.x), q1 = phi(qq.y),
              q2 = phi(qq.z), q3 = phi(qq.w);

        float z = q0 * pk.x + q1 * pk.y + q2 * pk.z + q3 * pk.w;
        z += __shfl_xor_sync(0xffffffffu, z, 8);
        z += __shfl_xor_sync(0xffffffffu, z, 4);
        z += __shfl_xor_sync(0xffffffffu, z, 2);
        z += __shfl_xor_sync(0xffffffffu, z, 1);
        z = (z + EPS_) * m;
        float rz = 1.0f / z;

        float4 o;
        o.x = q0 * pkv.x * rz; o.y = q1 * pkv.y * rz;
        o.z = q2 * pkv.z * rz; o.w = q3 * pkv.w * rz;
        st_stream4(op + off, o);
    }
}

// ---------------------------------------------------------------------------
extern "C" void kernel_launch(void* const* d_in, const int* in_sizes, int n_in,
                              void* d_out, int out_size)
{
    const float* q = (const float*)d_in[0];
    const float* k = (const float*)d_in[1];
    const float* v = (const float*)d_in[2];
    const float* m = (const float*)d_in[3];
    float* out = (float*)d_out;

    la_fused<<<NBLK_, 256>>>(q, k, v, m, out);
}